// round 4
// baseline (speedup 1.0000x reference)
#include <cuda_runtime.h>

#define N_NODES 100000
#define N_EDGES 1600000
#define F_IN 16
#define F_MID 32

#define SCAN_T 256
#define ELEMS_PER_BLOCK 1024
#define N_SCAN_BLOCKS ((N_NODES + ELEMS_PER_BLOCK - 1) / ELEMS_PER_BLOCK)  // 98
#define N_PAD (N_SCAN_BLOCKS * ELEMS_PER_BLOCK)                            // 100352

// Scratch (device globals; no allocation allowed)
__device__ __align__(16) int   g_cnt[N_PAD];              // in-degree histogram (memset 0)
__device__ unsigned long long  g_state[N_SCAN_BLOCKS];    // lookback {flag,val} (memset 0)
__device__ __align__(16) int   g_rp [N_NODES];            // CSR row pointers
__device__ __align__(16) int   g_pos[N_EDGES];            // per-edge slot within dst row
__device__ __align__(16) int   g_csr[N_EDGES];            // CSR column (src) indices
__device__ __align__(16) float g_dis[N_NODES];            // rsqrt(deg+1)
__device__ __align__(16) float g_xs [N_NODES * F_IN];     // dis[v] * x[v]
__device__ __align__(16) float g_AX [N_NODES * F_IN];     // aggregated scaled X
__device__ __align__(16) float g_h2s[N_NODES * 2];        // dis[v]*(relu(..)@W2)

// 1) histogram + per-edge slot in ONE atomic pass (4 edges/thread)
__global__ void k_hist_pos(const int* __restrict__ ei) {
    int t = blockIdx.x * blockDim.x + threadIdx.x;
    long e = (long)t * 4;
    if (e >= N_EDGES) return;
    int4 d4 = *(const int4*)(ei + N_EDGES + e);
    int4 p4;
    p4.x = atomicAdd(&g_cnt[d4.x], 1);
    p4.y = atomicAdd(&g_cnt[d4.y], 1);
    p4.z = atomicAdd(&g_cnt[d4.z], 1);
    p4.w = atomicAdd(&g_cnt[d4.w], 1);
    *(int4*)(g_pos + e) = p4;
}

// 2) single-pass decoupled-lookback scan -> g_rp, plus dis + xs scaling fused.
//    state[b] = (flag<<32)|value; flag 1 = block aggregate, 2 = inclusive prefix.
__global__ void k_scan_pre(const float* __restrict__ x) {
    __shared__ int   sdata[SCAN_T];
    __shared__ int   s_prefix;
    __shared__ float sdis[ELEMS_PER_BLOCK];
    int b = blockIdx.x;
    int t = threadIdx.x;
    long base = (long)b * ELEMS_PER_BLOCK + (long)t * 4;

    int4 c4 = *(const int4*)(g_cnt + base);
    int s = c4.x + c4.y + c4.z + c4.w;
    sdata[t] = s;
    __syncthreads();
    int incl = s;
#pragma unroll
    for (int off = 1; off < SCAN_T; off <<= 1) {
        int v = (t >= off) ? sdata[t - off] : 0;
        __syncthreads();
        incl += v;
        sdata[t] = incl;
        __syncthreads();
    }
    int total = sdata[SCAN_T - 1];

    // publish aggregate (block 0 publishes full prefix immediately)
    if (t == 0) {
        unsigned long long st =
            ((unsigned long long)(b == 0 ? 2 : 1) << 32) | (unsigned int)total;
        atomicExch(&g_state[b], st);
        if (b == 0) s_prefix = 0;
    }

    // warp-parallel lookback (warp 0)
    if (b > 0 && t < 32) {
        int tile = b - 1;
        int sum = 0;
        while (true) {
            int p = tile - t;
            int flag = 0, val = 0;
            if (p >= 0) {
                unsigned long long sl;
                do {
                    sl = atomicAdd(&g_state[p], 0ULL);
                    flag = (int)(sl >> 32);
                } while (flag == 0);
                val = (int)(unsigned int)sl;
            }
            unsigned ball = __ballot_sync(0xffffffffu, (p >= 0) && (flag == 2));
            if (ball) {
                int L = __ffs(ball) - 1;            // closest pred with full prefix
                int contrib = (t <= L) ? val : 0;
#pragma unroll
                for (int m = 16; m >= 1; m >>= 1)
                    contrib += __shfl_xor_sync(0xffffffffu, contrib, m);
                sum += contrib;
                break;
            } else {
                int contrib = (p >= 0) ? val : 0;
#pragma unroll
                for (int m = 16; m >= 1; m >>= 1)
                    contrib += __shfl_xor_sync(0xffffffffu, contrib, m);
                sum += contrib;
                tile -= 32;
            }
        }
        if (t == 0) {
            atomicExch(&g_state[b],
                       ((unsigned long long)2 << 32) | (unsigned int)(sum + total));
            s_prefix = sum;
        }
    }
    __syncthreads();

    // row pointers + dis for this block's 4 nodes/thread
    int excl = s_prefix + sdata[t] - s;
    long v0 = base;
    if (v0 < N_NODES) {
        int4 rp4;
        rp4.x = excl;
        rp4.y = rp4.x + c4.x;
        rp4.z = rp4.y + c4.y;
        rp4.w = rp4.z + c4.z;
        *(int4*)(g_rp + v0) = rp4;
        float4 d4;
        d4.x = rsqrtf((float)(c4.x + 1));
        d4.y = rsqrtf((float)(c4.y + 1));
        d4.z = rsqrtf((float)(c4.z + 1));
        d4.w = rsqrtf((float)(c4.w + 1));
        *(float4*)(g_dis + v0) = d4;
        sdis[t * 4 + 0] = d4.x; sdis[t * 4 + 1] = d4.y;
        sdis[t * 4 + 2] = d4.z; sdis[t * 4 + 3] = d4.w;
    }
    __syncthreads();

    // fused pre-scale: xs = dis * x for this block's nodes (coalesced float4)
    long node_base = (long)b * ELEMS_PER_BLOCK;
#pragma unroll
    for (int i = t; i < ELEMS_PER_BLOCK * 4; i += SCAN_T) {
        int nl = i >> 2;           // node within block
        long v = node_base + nl;
        if (v < N_NODES) {
            int q = i & 3;
            float dis = sdis[nl];
            float4 xv = *(const float4*)(x + v * F_IN + q * 4);
            xv.x *= dis; xv.y *= dis; xv.z *= dis; xv.w *= dis;
            *(float4*)(g_xs + v * F_IN + q * 4) = xv;
        }
    }
}

// 3) scatter edges into CSR (no atomics)
__global__ void k_scatter(const int* __restrict__ ei) {
    int t = blockIdx.x * blockDim.x + threadIdx.x;
    long e = (long)t * 4;
    if (e >= N_EDGES) return;
    int4 s4 = *(const int4*)(ei + e);
    int4 d4 = *(const int4*)(ei + N_EDGES + e);
    int4 p4 = *(const int4*)(g_pos + e);
    g_csr[g_rp[d4.x] + p4.x] = s4.x;
    g_csr[g_rp[d4.y] + p4.y] = s4.y;
    g_csr[g_rp[d4.z] + p4.z] = s4.z;
    g_csr[g_rp[d4.w] + p4.w] = s4.w;
}

// 4) layer-1 aggregation: warp per node, 8 edge-slots x 4 lanes, NO atomics
__global__ void k_agg1() {
    long gtid = (long)blockIdx.x * blockDim.x + threadIdx.x;
    int v = (int)(gtid >> 5);
    if (v >= N_NODES) return;
    int lane = threadIdx.x & 31;
    int slot = lane >> 2;
    int q    = lane & 3;
    int start = g_rp[v];
    int d     = g_cnt[v];
    float4 acc = make_float4(0.f, 0.f, 0.f, 0.f);
    for (int i = slot; i < d; i += 8) {
        int s = __ldg(g_csr + start + i);
        float4 w = *(const float4*)(g_xs + (long)s * F_IN + q * 4);
        acc.x += w.x; acc.y += w.y; acc.z += w.z; acc.w += w.w;
    }
    __syncwarp();
#pragma unroll
    for (int m = 16; m >= 4; m >>= 1) {
        acc.x += __shfl_xor_sync(0xffffffffu, acc.x, m);
        acc.y += __shfl_xor_sync(0xffffffffu, acc.y, m);
        acc.z += __shfl_xor_sync(0xffffffffu, acc.z, m);
        acc.w += __shfl_xor_sync(0xffffffffu, acc.w, m);
    }
    if (lane < 4) {  // q == lane
        float4 self = *(const float4*)(g_xs + (long)v * F_IN + lane * 4);
        acc.x += self.x; acc.y += self.y; acc.z += self.z; acc.w += self.w;
        *(float4*)(g_AX + (long)v * F_IN + lane * 4) = acc;
    }
}

// 5) fused epilogue: h2s = dis * (relu(dis*(AX@W1)+b1) @ W2)
__global__ void k_layer2(const float* __restrict__ W1, const float* __restrict__ b1,
                         const float* __restrict__ W2) {
    __shared__ float sW1[F_IN * F_MID];
    __shared__ float sb1[F_MID];
    __shared__ float sW2[F_MID * 2];
    int t = threadIdx.x;
    for (int i = t; i < F_IN * F_MID; i += blockDim.x) sW1[i] = W1[i];
    if (t < F_MID) sb1[t] = b1[t];
    if (t < F_MID * 2) sW2[t] = W2[t];
    __syncthreads();
    int v = blockIdx.x * blockDim.x + t;
    if (v >= N_NODES) return;
    float dis = g_dis[v];

    float ax[F_IN];
    const float4* Ar = (const float4*)(g_AX + (long)v * F_IN);
#pragma unroll
    for (int q = 0; q < 4; q++) {
        float4 a4 = Ar[q];
        ax[q * 4 + 0] = a4.x; ax[q * 4 + 1] = a4.y;
        ax[q * 4 + 2] = a4.z; ax[q * 4 + 3] = a4.w;
    }
    float h[F_MID];
#pragma unroll
    for (int j = 0; j < F_MID; j++) h[j] = 0.0f;
#pragma unroll
    for (int k = 0; k < F_IN; k++) {
        float a = ax[k];
#pragma unroll
        for (int j = 0; j < F_MID; j++) h[j] = fmaf(a, sW1[k * F_MID + j], h[j]);
    }
    float acc0 = 0.f, acc1 = 0.f;
#pragma unroll
    for (int j = 0; j < F_MID; j++) {
        float hj = fmaxf(fmaf(dis, h[j], sb1[j]), 0.0f);
        acc0 = fmaf(hj, sW2[j * 2 + 0], acc0);
        acc1 = fmaf(hj, sW2[j * 2 + 1], acc1);
    }
    *(float2*)(g_h2s + (long)v * 2) = make_float2(dis * acc0, dis * acc1);
}

// 6) layer-2 aggregation + final scale/bias fused: warp per node, 16 slots x 2 lanes
__global__ void k_agg2_out(const float* __restrict__ b2, float* __restrict__ out) {
    long gtid = (long)blockIdx.x * blockDim.x + threadIdx.x;
    int v = (int)(gtid >> 5);
    if (v >= N_NODES) return;
    int lane = threadIdx.x & 31;
    int slot = lane >> 1;
    int c    = lane & 1;
    int start = g_rp[v];
    int d     = g_cnt[v];
    float acc = 0.0f;
    for (int i = slot; i < d; i += 16) {
        int s = __ldg(g_csr + start + i);
        acc += g_h2s[(long)s * 2 + c];
    }
    __syncwarp();
#pragma unroll
    for (int m = 16; m >= 2; m >>= 1)
        acc += __shfl_xor_sync(0xffffffffu, acc, m);
    if (lane < 2) {  // c == lane
        float self = g_h2s[(long)v * 2 + lane];
        out[(long)v * 2 + lane] = fmaf(g_dis[v], acc + self, b2[lane]);
    }
}

extern "C" void kernel_launch(void* const* d_in, const int* in_sizes, int n_in,
                              void* d_out, int out_size) {
    const float* x  = (const float*)d_in[0];
    const int*   ei = (const int*)  d_in[1];
    const float* W1 = (const float*)d_in[2];
    const float* b1 = (const float*)d_in[3];
    const float* W2 = (const float*)d_in[4];
    const float* b2 = (const float*)d_in[5];
    float* out = (float*)d_out;

    // symbol addresses (host-side query, capture-safe; deterministic)
    static void* p_cnt = nullptr;
    static void* p_state = nullptr;
    if (!p_cnt) {
        cudaGetSymbolAddress(&p_cnt, g_cnt);
        cudaGetSymbolAddress(&p_state, g_state);
    }

    const int T = 256;
    cudaMemsetAsync(p_cnt, 0, N_PAD * sizeof(int));
    cudaMemsetAsync(p_state, 0, N_SCAN_BLOCKS * sizeof(unsigned long long));
    k_hist_pos<<<(N_EDGES / 4 + T - 1) / T, T>>>(ei);
    k_scan_pre<<<N_SCAN_BLOCKS, SCAN_T>>>(x);
    k_scatter<<<(N_EDGES / 4 + T - 1) / T, T>>>(ei);
    {
        long n = (long)N_NODES * 32;
        k_agg1<<<(unsigned)((n + T - 1) / T), T>>>();
    }
    k_layer2<<<(N_NODES + T - 1) / T, T>>>(W1, b1, W2);
    {
        long n = (long)N_NODES * 32;
        k_agg2_out<<<(unsigned)((n + T - 1) / T), T>>>(b2, out);
    }
}

// round 5
// speedup vs baseline: 1.1845x; 1.1845x over previous
#include <cuda_runtime.h>

#define N_NODES 100000
#define N_EDGES 1600000
#define F_IN 16
#define F_MID 32

#define SCAN_T 256
#define ELEMS_PER_BLOCK 1024
#define N_SCAN_BLOCKS ((N_NODES + ELEMS_PER_BLOCK - 1) / ELEMS_PER_BLOCK)  // 98
#define N_PAD (N_SCAN_BLOCKS * ELEMS_PER_BLOCK)                            // 100352

// Scratch (device globals; no allocation allowed)
__device__ __align__(16) int   g_cnt[N_PAD];              // in-degree histogram (memset 0)
__device__ unsigned long long  g_state[N_SCAN_BLOCKS];    // lookback {flag,val} (memset 0)
__device__ __align__(16) int   g_rp [N_NODES];            // CSR row pointers
__device__ __align__(16) int   g_pos[N_EDGES];            // per-edge slot within dst row
__device__ __align__(16) int   g_csr[N_EDGES];            // CSR column (src) indices
__device__ __align__(16) float g_dis[N_NODES];            // rsqrt(deg+1)
__device__ __align__(16) float g_xs [N_NODES * F_IN];     // dis[v] * x[v]
__device__ __align__(16) float g_h2s[N_NODES * 2];        // dis[v]*(relu(..)@W2)

// 1) histogram + per-edge slot in ONE atomic pass (4 edges/thread)
__global__ void k_hist_pos(const int* __restrict__ ei) {
    int t = blockIdx.x * blockDim.x + threadIdx.x;
    long e = (long)t * 4;
    if (e >= N_EDGES) return;
    int4 d4 = *(const int4*)(ei + N_EDGES + e);
    int4 p4;
    p4.x = atomicAdd(&g_cnt[d4.x], 1);
    p4.y = atomicAdd(&g_cnt[d4.y], 1);
    p4.z = atomicAdd(&g_cnt[d4.z], 1);
    p4.w = atomicAdd(&g_cnt[d4.w], 1);
    *(int4*)(g_pos + e) = p4;
}

// 2) single-pass decoupled-lookback scan -> g_rp, plus dis + xs scaling fused.
__global__ void k_scan_pre(const float* __restrict__ x) {
    __shared__ int   sdata[SCAN_T];
    __shared__ int   s_prefix;
    __shared__ float sdis[ELEMS_PER_BLOCK];
    int b = blockIdx.x;
    int t = threadIdx.x;
    long base = (long)b * ELEMS_PER_BLOCK + (long)t * 4;

    int4 c4 = *(const int4*)(g_cnt + base);
    int s = c4.x + c4.y + c4.z + c4.w;
    sdata[t] = s;
    __syncthreads();
    int incl = s;
#pragma unroll
    for (int off = 1; off < SCAN_T; off <<= 1) {
        int v = (t >= off) ? sdata[t - off] : 0;
        __syncthreads();
        incl += v;
        sdata[t] = incl;
        __syncthreads();
    }
    int total = sdata[SCAN_T - 1];

    if (t == 0) {
        unsigned long long st =
            ((unsigned long long)(b == 0 ? 2 : 1) << 32) | (unsigned int)total;
        atomicExch(&g_state[b], st);
        if (b == 0) s_prefix = 0;
    }

    if (b > 0 && t < 32) {
        int tile = b - 1;
        int sum = 0;
        while (true) {
            int p = tile - t;
            int flag = 0, val = 0;
            if (p >= 0) {
                unsigned long long sl;
                do {
                    sl = atomicAdd(&g_state[p], 0ULL);
                    flag = (int)(sl >> 32);
                } while (flag == 0);
                val = (int)(unsigned int)sl;
            }
            unsigned ball = __ballot_sync(0xffffffffu, (p >= 0) && (flag == 2));
            if (ball) {
                int L = __ffs(ball) - 1;
                int contrib = (t <= L) ? val : 0;
#pragma unroll
                for (int m = 16; m >= 1; m >>= 1)
                    contrib += __shfl_xor_sync(0xffffffffu, contrib, m);
                sum += contrib;
                break;
            } else {
                int contrib = (p >= 0) ? val : 0;
#pragma unroll
                for (int m = 16; m >= 1; m >>= 1)
                    contrib += __shfl_xor_sync(0xffffffffu, contrib, m);
                sum += contrib;
                tile -= 32;
            }
        }
        if (t == 0) {
            atomicExch(&g_state[b],
                       ((unsigned long long)2 << 32) | (unsigned int)(sum + total));
            s_prefix = sum;
        }
    }
    __syncthreads();

    int excl = s_prefix + sdata[t] - s;
    long v0 = base;
    if (v0 < N_NODES) {
        int4 rp4;
        rp4.x = excl;
        rp4.y = rp4.x + c4.x;
        rp4.z = rp4.y + c4.y;
        rp4.w = rp4.z + c4.z;
        *(int4*)(g_rp + v0) = rp4;
        float4 d4;
        d4.x = rsqrtf((float)(c4.x + 1));
        d4.y = rsqrtf((float)(c4.y + 1));
        d4.z = rsqrtf((float)(c4.z + 1));
        d4.w = rsqrtf((float)(c4.w + 1));
        *(float4*)(g_dis + v0) = d4;
        sdis[t * 4 + 0] = d4.x; sdis[t * 4 + 1] = d4.y;
        sdis[t * 4 + 2] = d4.z; sdis[t * 4 + 3] = d4.w;
    }
    __syncthreads();

    long node_base = (long)b * ELEMS_PER_BLOCK;
#pragma unroll
    for (int i = t; i < ELEMS_PER_BLOCK * 4; i += SCAN_T) {
        int nl = i >> 2;
        long v = node_base + nl;
        if (v < N_NODES) {
            int q = i & 3;
            float dis = sdis[nl];
            float4 xv = *(const float4*)(x + v * F_IN + q * 4);
            xv.x *= dis; xv.y *= dis; xv.z *= dis; xv.w *= dis;
            *(float4*)(g_xs + v * F_IN + q * 4) = xv;
        }
    }
}

// 3) scatter edges into CSR (no atomics)
__global__ void k_scatter(const int* __restrict__ ei) {
    int t = blockIdx.x * blockDim.x + threadIdx.x;
    long e = (long)t * 4;
    if (e >= N_EDGES) return;
    int4 s4 = *(const int4*)(ei + e);
    int4 d4 = *(const int4*)(ei + N_EDGES + e);
    int4 p4 = *(const int4*)(g_pos + e);
    g_csr[g_rp[d4.x] + p4.x] = s4.x;
    g_csr[g_rp[d4.y] + p4.y] = s4.y;
    g_csr[g_rp[d4.z] + p4.z] = s4.z;
    g_csr[g_rp[d4.w] + p4.w] = s4.w;
}

// 4) layer-1 aggregation + full layer-1/2 math fused.
//    4 lanes per node; lane q owns float4 quad q. Serial edge loop, unroll 4,
//    no reductions for the aggregation. GEMMs done in-register via shuffles.
__global__ void k_agg1_fused(const float* __restrict__ W1, const float* __restrict__ b1,
                             const float* __restrict__ W2) {
    __shared__ float sW1[F_IN * F_MID];
    __shared__ float sb1[F_MID];
    __shared__ float sW2[F_MID * 2];
    {
        int t = threadIdx.x;
        for (int i = t; i < F_IN * F_MID; i += blockDim.x) sW1[i] = W1[i];
        if (t < F_MID) sb1[t] = b1[t];
        if (t < F_MID * 2) sW2[t] = W2[t];
        __syncthreads();
    }
    long gtid = (long)blockIdx.x * blockDim.x + threadIdx.x;
    int v = (int)(gtid >> 2);
    if (v >= N_NODES) return;              // warps never straddle (100000*4 % 32 == 0)
    int lane = threadIdx.x & 31;
    int q = lane & 3;
    int q4 = q * 4;

    int start = g_rp[v];
    int d     = g_cnt[v];
    float dis = g_dis[v];

    // self-loop init
    float4 acc = *(const float4*)(g_xs + (long)v * F_IN + q4);

    const int* crow = g_csr + start;
    int i = 0;
    int d4 = d & ~3;
    for (; i < d4; i += 4) {
        int s0 = __ldg(crow + i + 0);
        int s1 = __ldg(crow + i + 1);
        int s2 = __ldg(crow + i + 2);
        int s3 = __ldg(crow + i + 3);
        float4 w0 = *(const float4*)(g_xs + (long)s0 * F_IN + q4);
        float4 w1 = *(const float4*)(g_xs + (long)s1 * F_IN + q4);
        float4 w2 = *(const float4*)(g_xs + (long)s2 * F_IN + q4);
        float4 w3 = *(const float4*)(g_xs + (long)s3 * F_IN + q4);
        acc.x += w0.x + w1.x + w2.x + w3.x;
        acc.y += w0.y + w1.y + w2.y + w3.y;
        acc.z += w0.z + w1.z + w2.z + w3.z;
        acc.w += w0.w + w1.w + w2.w + w3.w;
    }
    for (; i < d; i++) {
        int s = __ldg(crow + i);
        float4 w = *(const float4*)(g_xs + (long)s * F_IN + q4);
        acc.x += w.x; acc.y += w.y; acc.z += w.z; acc.w += w.w;
    }

    // GEMM1: each lane computes h columns [q*8, q*8+8). ax[k] lives on lane (k>>2).
    float h[8];
#pragma unroll
    for (int jj = 0; jj < 8; jj++) h[jj] = 0.0f;
    int gbase = lane & ~3;
#pragma unroll
    for (int k = 0; k < F_IN; k++) {
        float comp;
        switch (k & 3) {
            case 0: comp = acc.x; break;
            case 1: comp = acc.y; break;
            case 2: comp = acc.z; break;
            default: comp = acc.w; break;
        }
        float a = __shfl_sync(0xffffffffu, comp, gbase | (k >> 2));
#pragma unroll
        for (int jj = 0; jj < 8; jj++)
            h[jj] = fmaf(a, sW1[k * F_MID + q * 8 + jj], h[jj]);
    }

    // relu + GEMM2 partials, reduce over the 4-lane group
    float p0 = 0.f, p1 = 0.f;
#pragma unroll
    for (int jj = 0; jj < 8; jj++) {
        int j = q * 8 + jj;
        float hj = fmaxf(fmaf(dis, h[jj], sb1[j]), 0.0f);
        p0 = fmaf(hj, sW2[j * 2 + 0], p0);
        p1 = fmaf(hj, sW2[j * 2 + 1], p1);
    }
    p0 += __shfl_xor_sync(0xffffffffu, p0, 1);
    p0 += __shfl_xor_sync(0xffffffffu, p0, 2);
    p1 += __shfl_xor_sync(0xffffffffu, p1, 1);
    p1 += __shfl_xor_sync(0xffffffffu, p1, 2);
    if (q == 0)
        *(float2*)(g_h2s + (long)v * 2) = make_float2(dis * p0, dis * p1);
}

// 5) layer-2 aggregation + final scale/bias fused.
//    2 lanes per node; lane owns one output channel. Serial loop, unroll 4.
__global__ void k_agg2_out(const float* __restrict__ b2, float* __restrict__ out) {
    long gtid = (long)blockIdx.x * blockDim.x + threadIdx.x;
    int v = (int)(gtid >> 1);
    if (v >= N_NODES) return;
    int c = (int)(gtid & 1);

    int start = g_rp[v];
    int d     = g_cnt[v];

    float acc = g_h2s[(long)v * 2 + c];   // self loop
    const int* crow = g_csr + start;
    int i = 0;
    int d4 = d & ~3;
    for (; i < d4; i += 4) {
        int s0 = __ldg(crow + i + 0);
        int s1 = __ldg(crow + i + 1);
        int s2 = __ldg(crow + i + 2);
        int s3 = __ldg(crow + i + 3);
        acc += g_h2s[(long)s0 * 2 + c] + g_h2s[(long)s1 * 2 + c]
             + g_h2s[(long)s2 * 2 + c] + g_h2s[(long)s3 * 2 + c];
    }
    for (; i < d; i++) {
        int s = __ldg(crow + i);
        acc += g_h2s[(long)s * 2 + c];
    }
    out[(long)v * 2 + c] = fmaf(g_dis[v], acc, b2[c]);
}

extern "C" void kernel_launch(void* const* d_in, const int* in_sizes, int n_in,
                              void* d_out, int out_size) {
    const float* x  = (const float*)d_in[0];
    const int*   ei = (const int*)  d_in[1];
    const float* W1 = (const float*)d_in[2];
    const float* b1 = (const float*)d_in[3];
    const float* W2 = (const float*)d_in[4];
    const float* b2 = (const float*)d_in[5];
    float* out = (float*)d_out;

    static void* p_cnt = nullptr;
    static void* p_state = nullptr;
    if (!p_cnt) {
        cudaGetSymbolAddress(&p_cnt, g_cnt);
        cudaGetSymbolAddress(&p_state, g_state);
    }

    const int T = 256;
    cudaMemsetAsync(p_cnt, 0, N_PAD * sizeof(int));
    cudaMemsetAsync(p_state, 0, N_SCAN_BLOCKS * sizeof(unsigned long long));
    k_hist_pos<<<(N_EDGES / 4 + T - 1) / T, T>>>(ei);
    k_scan_pre<<<N_SCAN_BLOCKS, SCAN_T>>>(x);
    k_scatter<<<(N_EDGES / 4 + T - 1) / T, T>>>(ei);
    {
        long n = (long)N_NODES * 4;
        k_agg1_fused<<<(unsigned)((n + T - 1) / T), T>>>(W1, b1, W2);
    }
    {
        long n = (long)N_NODES * 2;
        k_agg2_out<<<(unsigned)((n + T - 1) / T), T>>>(b2, out);
    }
}

// round 6
// speedup vs baseline: 1.2354x; 1.0430x over previous
#include <cuda_runtime.h>

#define N_NODES 100000
#define N_EDGES 1600000
#define F_IN 16
#define F_MID 32

#define SCAN_T 256
#define ELEMS_PER_BLOCK 1024
#define N_SCAN_BLOCKS ((N_NODES + ELEMS_PER_BLOCK - 1) / ELEMS_PER_BLOCK)  // 98
#define N_PAD (N_SCAN_BLOCKS * ELEMS_PER_BLOCK)                            // 100352

// Zeroed-every-iteration region: ONE memset covers both
struct ZBuf {
    int cnt[N_PAD];
    unsigned long long state[N_SCAN_BLOCKS];
};
__device__ __align__(16) ZBuf g_z;

__device__ __align__(16) int   g_rp [N_NODES];            // CSR row pointers
__device__ __align__(16) int   g_pos[N_EDGES];            // per-edge slot within dst row
__device__ __align__(16) int   g_csr[N_EDGES];            // CSR column (src) indices
__device__ __align__(16) float g_dis[N_NODES];            // rsqrt(deg+1)
__device__ __align__(16) float g_xs [N_NODES * F_IN];     // dis[v] * x[v]
__device__ __align__(16) float g_h2s[N_NODES * 2];        // dis[v]*(relu(..)@W2)

// 1) histogram + per-edge slot in ONE atomic pass (4 edges/thread)
__global__ void k_hist_pos(const int* __restrict__ ei) {
    int t = blockIdx.x * blockDim.x + threadIdx.x;
    long e = (long)t * 4;
    if (e >= N_EDGES) return;
    int4 d4 = *(const int4*)(ei + N_EDGES + e);
    int4 p4;
    p4.x = atomicAdd(&g_z.cnt[d4.x], 1);
    p4.y = atomicAdd(&g_z.cnt[d4.y], 1);
    p4.z = atomicAdd(&g_z.cnt[d4.z], 1);
    p4.w = atomicAdd(&g_z.cnt[d4.w], 1);
    *(int4*)(g_pos + e) = p4;
}

// 2) single-pass decoupled-lookback scan -> g_rp, plus dis + xs scaling fused.
__global__ void k_scan_pre(const float* __restrict__ x) {
    __shared__ int   sdata[SCAN_T];
    __shared__ int   s_prefix;
    __shared__ float sdis[ELEMS_PER_BLOCK];
    int b = blockIdx.x;
    int t = threadIdx.x;
    long base = (long)b * ELEMS_PER_BLOCK + (long)t * 4;

    int4 c4 = *(const int4*)(g_z.cnt + base);
    int s = c4.x + c4.y + c4.z + c4.w;
    sdata[t] = s;
    __syncthreads();
    int incl = s;
#pragma unroll
    for (int off = 1; off < SCAN_T; off <<= 1) {
        int v = (t >= off) ? sdata[t - off] : 0;
        __syncthreads();
        incl += v;
        sdata[t] = incl;
        __syncthreads();
    }
    int total = sdata[SCAN_T - 1];

    if (t == 0) {
        unsigned long long st =
            ((unsigned long long)(b == 0 ? 2 : 1) << 32) | (unsigned int)total;
        atomicExch(&g_z.state[b], st);
        if (b == 0) s_prefix = 0;
    }

    if (b > 0 && t < 32) {
        int tile = b - 1;
        int sum = 0;
        while (true) {
            int p = tile - t;
            int flag = 0, val = 0;
            if (p >= 0) {
                unsigned long long sl;
                do {
                    sl = atomicAdd(&g_z.state[p], 0ULL);
                    flag = (int)(sl >> 32);
                } while (flag == 0);
                val = (int)(unsigned int)sl;
            }
            unsigned ball = __ballot_sync(0xffffffffu, (p >= 0) && (flag == 2));
            if (ball) {
                int L = __ffs(ball) - 1;
                int contrib = (t <= L) ? val : 0;
#pragma unroll
                for (int m = 16; m >= 1; m >>= 1)
                    contrib += __shfl_xor_sync(0xffffffffu, contrib, m);
                sum += contrib;
                break;
            } else {
                int contrib = (p >= 0) ? val : 0;
#pragma unroll
                for (int m = 16; m >= 1; m >>= 1)
                    contrib += __shfl_xor_sync(0xffffffffu, contrib, m);
                sum += contrib;
                tile -= 32;
            }
        }
        if (t == 0) {
            atomicExch(&g_z.state[b],
                       ((unsigned long long)2 << 32) | (unsigned int)(sum + total));
            s_prefix = sum;
        }
    }
    __syncthreads();

    int excl = s_prefix + sdata[t] - s;
    long v0 = base;
    if (v0 < N_NODES) {
        int4 rp4;
        rp4.x = excl;
        rp4.y = rp4.x + c4.x;
        rp4.z = rp4.y + c4.y;
        rp4.w = rp4.z + c4.z;
        *(int4*)(g_rp + v0) = rp4;
        float4 d4;
        d4.x = rsqrtf((float)(c4.x + 1));
        d4.y = rsqrtf((float)(c4.y + 1));
        d4.z = rsqrtf((float)(c4.z + 1));
        d4.w = rsqrtf((float)(c4.w + 1));
        *(float4*)(g_dis + v0) = d4;
        sdis[t * 4 + 0] = d4.x; sdis[t * 4 + 1] = d4.y;
        sdis[t * 4 + 2] = d4.z; sdis[t * 4 + 3] = d4.w;
    }
    __syncthreads();

    long node_base = (long)b * ELEMS_PER_BLOCK;
#pragma unroll
    for (int i = t; i < ELEMS_PER_BLOCK * 4; i += SCAN_T) {
        int nl = i >> 2;
        long v = node_base + nl;
        if (v < N_NODES) {
            int q = i & 3;
            float dis = sdis[nl];
            float4 xv = *(const float4*)(x + v * F_IN + q * 4);
            xv.x *= dis; xv.y *= dis; xv.z *= dis; xv.w *= dis;
            *(float4*)(g_xs + v * F_IN + q * 4) = xv;
        }
    }
}

// 3) scatter edges into CSR (no atomics)
__global__ void k_scatter(const int* __restrict__ ei) {
    int t = blockIdx.x * blockDim.x + threadIdx.x;
    long e = (long)t * 4;
    if (e >= N_EDGES) return;
    int4 s4 = *(const int4*)(ei + e);
    int4 d4 = *(const int4*)(ei + N_EDGES + e);
    int4 p4 = *(const int4*)(g_pos + e);
    g_csr[g_rp[d4.x] + p4.x] = s4.x;
    g_csr[g_rp[d4.y] + p4.y] = s4.y;
    g_csr[g_rp[d4.z] + p4.z] = s4.z;
    g_csr[g_rp[d4.w] + p4.w] = s4.w;
}

// 4) layer-1 aggregation + layer-1/2 math fused. 4-lane groups, GRID-STRIDE
//    over nodes (balances degree variance across warps). Unroll 8 for MLP.
#define AGG1_BLOCKS 592
__global__ void __launch_bounds__(256) k_agg1_fused(
        const float* __restrict__ W1, const float* __restrict__ b1,
        const float* __restrict__ W2) {
    __shared__ float sW1[F_IN * F_MID];
    __shared__ float sb1[F_MID];
    __shared__ float sW2[F_MID * 2];
    {
        int t = threadIdx.x;
        for (int i = t; i < F_IN * F_MID; i += blockDim.x) sW1[i] = W1[i];
        if (t < F_MID) sb1[t] = b1[t];
        if (t < F_MID * 2) sW2[t] = W2[t];
        __syncthreads();
    }
    int lane = threadIdx.x & 31;
    int q = lane & 3;
    int q4 = q * 4;
    unsigned gmask = 0xFu << (lane & ~3);     // this 4-lane group's mask
    int gbase = lane & ~3;

    int gid = (int)(((long)blockIdx.x * blockDim.x + threadIdx.x) >> 2);
    const int n_groups = AGG1_BLOCKS * 256 / 4;

    for (int v = gid; v < N_NODES; v += n_groups) {
        int start = g_rp[v];
        int d     = g_z.cnt[v];
        float dis = g_dis[v];

        float4 acc = *(const float4*)(g_xs + (long)v * F_IN + q4);  // self loop

        const int* crow = g_csr + start;
        int i = 0;
        int d8 = d & ~7;
        for (; i < d8; i += 8) {
            int s0 = __ldg(crow + i + 0);
            int s1 = __ldg(crow + i + 1);
            int s2 = __ldg(crow + i + 2);
            int s3 = __ldg(crow + i + 3);
            int s4 = __ldg(crow + i + 4);
            int s5 = __ldg(crow + i + 5);
            int s6 = __ldg(crow + i + 6);
            int s7 = __ldg(crow + i + 7);
            float4 w0 = *(const float4*)(g_xs + (long)s0 * F_IN + q4);
            float4 w1 = *(const float4*)(g_xs + (long)s1 * F_IN + q4);
            float4 w2 = *(const float4*)(g_xs + (long)s2 * F_IN + q4);
            float4 w3 = *(const float4*)(g_xs + (long)s3 * F_IN + q4);
            float4 w4 = *(const float4*)(g_xs + (long)s4 * F_IN + q4);
            float4 w5 = *(const float4*)(g_xs + (long)s5 * F_IN + q4);
            float4 w6 = *(const float4*)(g_xs + (long)s6 * F_IN + q4);
            float4 w7 = *(const float4*)(g_xs + (long)s7 * F_IN + q4);
            acc.x += (w0.x + w1.x) + (w2.x + w3.x) + ((w4.x + w5.x) + (w6.x + w7.x));
            acc.y += (w0.y + w1.y) + (w2.y + w3.y) + ((w4.y + w5.y) + (w6.y + w7.y));
            acc.z += (w0.z + w1.z) + (w2.z + w3.z) + ((w4.z + w5.z) + (w6.z + w7.z));
            acc.w += (w0.w + w1.w) + (w2.w + w3.w) + ((w4.w + w5.w) + (w6.w + w7.w));
        }
        for (; i < d; i++) {
            int s = __ldg(crow + i);
            float4 w = *(const float4*)(g_xs + (long)s * F_IN + q4);
            acc.x += w.x; acc.y += w.y; acc.z += w.z; acc.w += w.w;
        }

        // GEMM1: lane computes h columns [q*8, q*8+8); ax[k] on lane (gbase|(k>>2))
        float h[8];
#pragma unroll
        for (int jj = 0; jj < 8; jj++) h[jj] = 0.0f;
#pragma unroll
        for (int k = 0; k < F_IN; k++) {
            float comp;
            switch (k & 3) {
                case 0: comp = acc.x; break;
                case 1: comp = acc.y; break;
                case 2: comp = acc.z; break;
                default: comp = acc.w; break;
            }
            float a = __shfl_sync(gmask, comp, gbase | (k >> 2));
#pragma unroll
            for (int jj = 0; jj < 8; jj++)
                h[jj] = fmaf(a, sW1[k * F_MID + q * 8 + jj], h[jj]);
        }

        float p0 = 0.f, p1 = 0.f;
#pragma unroll
        for (int jj = 0; jj < 8; jj++) {
            int j = q * 8 + jj;
            float hj = fmaxf(fmaf(dis, h[jj], sb1[j]), 0.0f);
            p0 = fmaf(hj, sW2[j * 2 + 0], p0);
            p1 = fmaf(hj, sW2[j * 2 + 1], p1);
        }
        p0 += __shfl_xor_sync(gmask, p0, 1);
        p0 += __shfl_xor_sync(gmask, p0, 2);
        p1 += __shfl_xor_sync(gmask, p1, 1);
        p1 += __shfl_xor_sync(gmask, p1, 2);
        if (q == 0)
            *(float2*)(g_h2s + (long)v * 2) = make_float2(dis * p0, dis * p1);
    }
}

// 5) layer-2 aggregation + final scale/bias fused. 2-lane groups, grid-stride.
#define AGG2_BLOCKS 592
__global__ void __launch_bounds__(256) k_agg2_out(
        const float* __restrict__ b2, float* __restrict__ out) {
    int c = (int)(threadIdx.x & 1);
    int gid = (int)(((long)blockIdx.x * blockDim.x + threadIdx.x) >> 1);
    const int n_groups = AGG2_BLOCKS * 256 / 2;
    float bias = b2[c];

    for (int v = gid; v < N_NODES; v += n_groups) {
        int start = g_rp[v];
        int d     = g_z.cnt[v];

        float acc = g_h2s[(long)v * 2 + c];   // self loop
        const int* crow = g_csr + start;
        int i = 0;
        int d8 = d & ~7;
        for (; i < d8; i += 8) {
            int s0 = __ldg(crow + i + 0);
            int s1 = __ldg(crow + i + 1);
            int s2 = __ldg(crow + i + 2);
            int s3 = __ldg(crow + i + 3);
            int s4 = __ldg(crow + i + 4);
            int s5 = __ldg(crow + i + 5);
            int s6 = __ldg(crow + i + 6);
            int s7 = __ldg(crow + i + 7);
            float a0 = g_h2s[(long)s0 * 2 + c];
            float a1 = g_h2s[(long)s1 * 2 + c];
            float a2 = g_h2s[(long)s2 * 2 + c];
            float a3 = g_h2s[(long)s3 * 2 + c];
            float a4 = g_h2s[(long)s4 * 2 + c];
            float a5 = g_h2s[(long)s5 * 2 + c];
            float a6 = g_h2s[(long)s6 * 2 + c];
            float a7 = g_h2s[(long)s7 * 2 + c];
            acc += (a0 + a1) + (a2 + a3) + ((a4 + a5) + (a6 + a7));
        }
        for (; i < d; i++) {
            int s = __ldg(crow + i);
            acc += g_h2s[(long)s * 2 + c];
        }
        out[(long)v * 2 + c] = fmaf(g_dis[v], acc, bias);
    }
}

extern "C" void kernel_launch(void* const* d_in, const int* in_sizes, int n_in,
                              void* d_out, int out_size) {
    const float* x  = (const float*)d_in[0];
    const int*   ei = (const int*)  d_in[1];
    const float* W1 = (const float*)d_in[2];
    const float* b1 = (const float*)d_in[3];
    const float* W2 = (const float*)d_in[4];
    const float* b2 = (const float*)d_in[5];
    float* out = (float*)d_out;

    static void* p_z = nullptr;
    if (!p_z) cudaGetSymbolAddress(&p_z, g_z);

    const int T = 256;
    cudaMemsetAsync(p_z, 0, sizeof(ZBuf));
    k_hist_pos<<<(N_EDGES / 4 + T - 1) / T, T>>>(ei);
    k_scan_pre<<<N_SCAN_BLOCKS, SCAN_T>>>(x);
    k_scatter<<<(N_EDGES / 4 + T - 1) / T, T>>>(ei);
    k_agg1_fused<<<AGG1_BLOCKS, T>>>(W1, b1, W2);
    k_agg2_out<<<AGG2_BLOCKS, T>>>(b2, out);
}